// round 3
// baseline (speedup 1.0000x reference)
#include <cuda_runtime.h>
#include <cuda_bf16.h>
#include <math.h>

// ---------------- constants ----------------
#define BATCH 4
#define NPIX  4096          // 64*64
#define ROWS  16384         // BATCH*NPIX
#define DIM   192
#define DEPTH 6
#define HEADS 8
#define DH    64
#define INNER 512
#define FF    768
#define MFEAT 266
#define MP    272           // padded feature dim (mult of 16)
#define BHN   32            // BATCH*HEADS

__device__ __forceinline__ float gelu_exact(float x) {
    return 0.5f * x * (1.0f + erff(x * 0.70710678118654752f));
}
__device__ __forceinline__ float warpSum(float v) {
    #pragma unroll
    for (int o = 16; o; o >>= 1) v += __shfl_xor_sync(0xffffffffu, v, o);
    return v;
}
__device__ __forceinline__ float warpMax(float v) {
    #pragma unroll
    for (int o = 16; o; o >>= 1) v = fmaxf(v, __shfl_xor_sync(0xffffffffu, v, o));
    return v;
}

// ---------------- scratch (device globals; no allocs allowed) ----------------
__device__ float g_h   [ROWS * DIM];
__device__ float g_hn  [ROWS * DIM];
__device__ float g_q   [ROWS * INNER];
__device__ float g_k   [ROWS * INNER];
__device__ float g_v   [ROWS * INNER];
__device__ float g_qp  [(long)BHN * NPIX * MP];   // dd_q -> qp in place
__device__ float g_kp  [(long)BHN * NPIX * MP];   // dd_k -> kp in place
__device__ float g_ctx [BHN * MP * DH];
__device__ float g_ksum[BHN * MP];
__device__ float g_kmax[BHN];
__device__ float g_kmpart[BHN * 32];
__device__ float g_kspart[BHN * 8 * MP];
__device__ float g_denom[BHN * NPIX];
__device__ float g_attn[ROWS * INNER];
__device__ float g_ff  [ROWS * FF];
__device__ float g_t1  [ROWS * DIM];
__device__ float g_t2  [ROWS * DIM];
__device__ float g_y   [ROWS * DIM];
__device__ float g_nchw[BATCH * 192 * 64 * 64];
__device__ float g_c9o [BATCH * 192 * 64 * 64];
__device__ float g_c7o [BATCH * 96 * 64 * 64];
__device__ float g_c5o [BATCH * 48 * 64 * 64];

// ---------------- embed: h = x @ Win^T + bin + pos ----------------
__global__ void embed_kernel(const float* __restrict__ x, const float* __restrict__ W,
                             const float* __restrict__ bias, const float* __restrict__ pos,
                             float* __restrict__ H) {
    int row = blockIdx.x;           // b*4096 + n
    int c = threadIdx.x;            // 0..191
    int n = row & (NPIX - 1);
    const float* xr = x + (long)row * 3;
    float v = bias[c] + xr[0] * W[c * 3 + 0] + xr[1] * W[c * 3 + 1] + xr[2] * W[c * 3 + 2]
            + pos[(long)n * DIM + c];
    H[(long)row * DIM + c] = v;
}

// ---------------- scalenorm (g scalar per layer) ----------------
__global__ void scalenorm_kernel(const float* __restrict__ in, float* __restrict__ out,
                                 const float* __restrict__ gArr, int gIdx) {
    int w = (blockIdx.x * blockDim.x + threadIdx.x) >> 5;   // row
    int lane = threadIdx.x & 31;
    if (w >= ROWS) return;
    const float* r = in + (long)w * DIM;
    float ss = 0.f;
    #pragma unroll
    for (int c = lane; c < DIM; c += 32) { float v = r[c]; ss += v * v; }
    ss = warpSum(ss);
    float nrm = sqrtf(ss) * 0.07216878364870323f;  // 192^-0.5
    float s = gArr[gIdx] / fmaxf(nrm, 1e-5f);
    #pragma unroll
    for (int c = lane; c < DIM; c += 32) out[(long)w * DIM + c] = r[c] * s;
}

// ---------------- main SGEMM: C[M,N] = A[M,K] @ B[N,K]^T, BM=128 BN=64 BK=16 ----------------
// EPI: 0 none, 1 +bias, 2 gelu(+bias), 3 +bias+resid
template<int EPI>
__global__ void __launch_bounds__(256) gemm_nt(
    const float* __restrict__ A, const float* __restrict__ B,
    const float* __restrict__ bias, const float* __restrict__ resid,
    float* __restrict__ C, int M, int N, int K) {
    __shared__ float As[16][128];
    __shared__ float Bs[16][64];
    const int tid = threadIdx.x;
    const int bm = blockIdx.x * 128;
    const int bn = blockIdx.y * 64;
    const int tx = tid & 15, ty = tid >> 4;
    float acc[8][4] = {};
    const float* Ab = A + (long)bm * K;
    const float* Bb = B + (long)bn * K;
    for (int k0 = 0; k0 < K; k0 += 16) {
        #pragma unroll
        for (int i = 0; i < 2; i++) {
            int s = tid + i * 256;
            int r = s >> 2, c4 = (s & 3) << 2;
            float4 v = *(const float4*)(Ab + (long)r * K + k0 + c4);
            As[c4 + 0][r] = v.x; As[c4 + 1][r] = v.y; As[c4 + 2][r] = v.z; As[c4 + 3][r] = v.w;
        }
        {
            int r = tid >> 2, c4 = (tid & 3) << 2;
            float4 v = *(const float4*)(Bb + (long)r * K + k0 + c4);
            Bs[c4 + 0][r] = v.x; Bs[c4 + 1][r] = v.y; Bs[c4 + 2][r] = v.z; Bs[c4 + 3][r] = v.w;
        }
        __syncthreads();
        #pragma unroll
        for (int kk = 0; kk < 16; kk++) {
            float a[8], bb[4];
            *(float4*)&a[0] = *(const float4*)&As[kk][ty * 8];
            *(float4*)&a[4] = *(const float4*)&As[kk][ty * 8 + 4];
            *(float4*)&bb[0] = *(const float4*)&Bs[kk][tx * 4];
            #pragma unroll
            for (int i = 0; i < 8; i++)
                #pragma unroll
                for (int j = 0; j < 4; j++)
                    acc[i][j] = fmaf(a[i], bb[j], acc[i][j]);
        }
        __syncthreads();
    }
    #pragma unroll
    for (int i = 0; i < 8; i++) {
        int row = bm + ty * 8 + i;
        #pragma unroll
        for (int j = 0; j < 4; j++) {
            int col = bn + tx * 4 + j;
            float v = acc[i][j];
            if (EPI >= 1) v += bias[col];
            if (EPI == 2) v = gelu_exact(v);
            if (EPI == 3) v += resid[(long)row * N + col];
            C[(long)row * N + col] = v;
        }
    }
}

// ---------------- dd GEMM (batched over b,h): dd[n,m] = dn * q[n,:64] . proj[m,:64] ----------------
__global__ void __launch_bounds__(256) gemm_dd(
    const float* __restrict__ Q, const float* __restrict__ P, float* __restrict__ DD) {
    __shared__ float As[16][128];
    __shared__ float Bs[16][64];
    const int tid = threadIdx.x;
    const int bh = blockIdx.z;
    const int b = bh >> 3, hh = bh & 7;
    const float* A = Q + ((long)b * NPIX) * INNER + hh * DH;   // lda = INNER
    float* C = DD + (long)bh * NPIX * MP;
    const int bm = blockIdx.x * 128, bn = blockIdx.y * 64;
    const int tx = tid & 15, ty = tid >> 4;
    float acc[8][4] = {};
    for (int k0 = 0; k0 < DH; k0 += 16) {
        #pragma unroll
        for (int i = 0; i < 2; i++) {
            int s = tid + i * 256;
            int r = s >> 2, c4 = (s & 3) << 2;
            float4 v = *(const float4*)(A + (long)(bm + r) * INNER + k0 + c4);
            As[c4 + 0][r] = v.x; As[c4 + 1][r] = v.y; As[c4 + 2][r] = v.z; As[c4 + 3][r] = v.w;
        }
        {
            int r = tid >> 2, c4 = (tid & 3) << 2;
            int m = bn + r;
            float4 v = make_float4(0.f, 0.f, 0.f, 0.f);
            if (m < MFEAT) v = *(const float4*)(P + (long)m * DH + k0 + c4);
            Bs[c4 + 0][r] = v.x; Bs[c4 + 1][r] = v.y; Bs[c4 + 2][r] = v.z; Bs[c4 + 3][r] = v.w;
        }
        __syncthreads();
        #pragma unroll
        for (int kk = 0; kk < 16; kk++) {
            float a[8], bb[4];
            *(float4*)&a[0] = *(const float4*)&As[kk][ty * 8];
            *(float4*)&a[4] = *(const float4*)&As[kk][ty * 8 + 4];
            *(float4*)&bb[0] = *(const float4*)&Bs[kk][tx * 4];
            #pragma unroll
            for (int i = 0; i < 8; i++)
                #pragma unroll
                for (int j = 0; j < 4; j++)
                    acc[i][j] = fmaf(a[i], bb[j], acc[i][j]);
        }
        __syncthreads();
    }
    const float dn = 0.35355339059327373f;  // 64^-0.25
    #pragma unroll
    for (int i = 0; i < 8; i++) {
        int row = bm + ty * 8 + i;
        #pragma unroll
        for (int j = 0; j < 4; j++) {
            int col = bn + tx * 4 + j;
            if (col < MFEAT) C[(long)row * MP + col] = dn * acc[i][j];
        }
    }
}

// ---------------- key global max (2-stage, deterministic) ----------------
__global__ void kmax_part_kernel(const float* __restrict__ DD, float* __restrict__ part) {
    int bh = blockIdx.y, slice = blockIdx.x;  // 32 slices of 128 rows
    const float* p = DD + (long)bh * NPIX * MP + (long)slice * 128 * MP;
    float m = -1e30f;
    for (int n = 0; n < 128; n++) {
        const float* r = p + (long)n * MP;
        for (int mm = threadIdx.x; mm < MFEAT; mm += 256) m = fmaxf(m, r[mm]);
    }
    __shared__ float sm[256];
    sm[threadIdx.x] = m; __syncthreads();
    for (int s = 128; s > 0; s >>= 1) {
        if (threadIdx.x < s) sm[threadIdx.x] = fmaxf(sm[threadIdx.x], sm[threadIdx.x + s]);
        __syncthreads();
    }
    if (threadIdx.x == 0) part[bh * 32 + slice] = sm[0];
}
__global__ void kmax_fin_kernel(const float* __restrict__ part, float* __restrict__ kmax) {
    float v = part[blockIdx.x * 32 + threadIdx.x];
    v = warpMax(v);
    if (threadIdx.x == 0) kmax[blockIdx.x] = v;
}

// ---------------- finalize features: dd -> ratio*(exp(dd - diag - mx) + eps); pads -> 0 ----------------
template<bool IS_QUERY>
__global__ void finalize_kernel(const float* __restrict__ QKV, float* __restrict__ DD,
                                const float* __restrict__ KM) {
    int w = (blockIdx.x * blockDim.x + threadIdx.x) >> 5;  // (bh,n) row
    int lane = threadIdx.x & 31;
    int bh = w >> 12, n = w & (NPIX - 1);
    int b = bh >> 3, hh = bh & 7;
    const float* q = QKV + ((long)(b * NPIX + n)) * INNER + hh * DH;
    float ss = 0.f;
    #pragma unroll
    for (int d = lane; d < DH; d += 32) { float v = q[d]; ss += v * v; }
    ss = warpSum(ss);
    float diag = 0.0625f * ss;                 // 0.5 * ss * 64^-0.5
    float* row = DD + (long)bh * NPIX * MP + (long)n * MP;
    float vals[9];
    float mx = -1e30f;
    #pragma unroll
    for (int i = 0; i < 9; i++) {
        int m = lane + i * 32;
        if (m < MFEAT) { vals[i] = row[m]; mx = fmaxf(mx, vals[i]); }
    }
    if (IS_QUERY) mx = warpMax(mx);
    else          mx = KM[bh];
    const float ratio = 0.06131393394849658f;  // 266^-0.5
    #pragma unroll
    for (int i = 0; i < 9; i++) {
        int m = lane + i * 32;
        if (m < MP)
            row[m] = (m < MFEAT) ? ratio * (expf(vals[i] - diag - mx) + 1e-4f) : 0.f;
    }
}

// ---------------- context[m,d] = sum_n kp[n,m] * v[n,d]   (per b,h) ----------------
__global__ void __launch_bounds__(256) gemm_ctx(
    const float* __restrict__ KP, const float* __restrict__ V, float* __restrict__ CT) {
    __shared__ float Ks[16][64];
    __shared__ float Vs[16][64];
    const int tid = threadIdx.x;
    const int bh = blockIdx.z;
    const int b = bh >> 3, hh = bh & 7;
    const float* kpB = KP + (long)bh * NPIX * MP;
    const float* vB = V + ((long)b * NPIX) * INNER + hh * DH;
    const int m0 = blockIdx.x * 64;
    const int tx = tid & 15, ty = tid >> 4;
    float acc[4][4] = {};
    for (int n0 = 0; n0 < NPIX; n0 += 16) {
        {
            int nn = tid >> 4, m4 = (tid & 15) << 2;
            float4 v = make_float4(0.f, 0.f, 0.f, 0.f);
            if (m0 + m4 < MP) v = *(const float4*)(kpB + (long)(n0 + nn) * MP + m0 + m4);
            Ks[nn][m4 + 0] = v.x; Ks[nn][m4 + 1] = v.y; Ks[nn][m4 + 2] = v.z; Ks[nn][m4 + 3] = v.w;
        }
        {
            int nn = tid >> 4, d4 = (tid & 15) << 2;
            float4 v = *(const float4*)(vB + (long)(n0 + nn) * INNER + d4);
            Vs[nn][d4 + 0] = v.x; Vs[nn][d4 + 1] = v.y; Vs[nn][d4 + 2] = v.z; Vs[nn][d4 + 3] = v.w;
        }
        __syncthreads();
        #pragma unroll
        for (int kk = 0; kk < 16; kk++) {
            float a[4], bb[4];
            *(float4*)&a[0] = *(const float4*)&Ks[kk][ty * 4];
            *(float4*)&bb[0] = *(const float4*)&Vs[kk][tx * 4];
            #pragma unroll
            for (int i = 0; i < 4; i++)
                #pragma unroll
                for (int j = 0; j < 4; j++)
                    acc[i][j] = fmaf(a[i], bb[j], acc[i][j]);
        }
        __syncthreads();
    }
    #pragma unroll
    for (int i = 0; i < 4; i++) {
        int m = m0 + ty * 4 + i;
        if (m < MP) {
            #pragma unroll
            for (int j = 0; j < 4; j++) {
                int d = tx * 4 + j;
                CT[((long)bh * MP + m) * DH + d] = acc[i][j];
            }
        }
    }
}

// ---------------- ksum (2-stage deterministic) ----------------
__global__ void ksum_part_kernel(const float* __restrict__ KP, float* __restrict__ part) {
    int bh = blockIdx.y, sl = blockIdx.x;  // 8 slices of 512 rows
    int m = threadIdx.x;                   // 272 threads
    const float* p = KP + (long)bh * NPIX * MP + (long)sl * 512 * MP + m;
    float s = 0.f;
    #pragma unroll 4
    for (int n = 0; n < 512; n++) s += p[(long)n * MP];
    part[((long)bh * 8 + sl) * MP + m] = s;
}
__global__ void ksum_fin_kernel(const float* __restrict__ part, float* __restrict__ ksum) {
    int bh = blockIdx.x, m = threadIdx.x;
    float s = 0.f;
    #pragma unroll
    for (int sl = 0; sl < 8; sl++) s += part[((long)bh * 8 + sl) * MP + m];
    ksum[bh * MP + m] = s;
}

// ---------------- denom[n] = sum_m qp[n,m] * ksum[m] ----------------
__global__ void denom_kernel(const float* __restrict__ QP, const float* __restrict__ KS,
                             float* __restrict__ D) {
    int w = (blockIdx.x * blockDim.x + threadIdx.x) >> 5;
    int lane = threadIdx.x & 31;
    int bh = w >> 12, n = w & (NPIX - 1);
    const float* row = QP + (long)bh * NPIX * MP + (long)n * MP;
    const float* ks = KS + bh * MP;
    float s = 0.f;
    #pragma unroll
    for (int i = 0; i < 9; i++) {
        int m = lane + i * 32;
        if (m < MP) s += row[m] * ks[m];
    }
    s = warpSum(s);
    if (lane == 0) D[bh * NPIX + n] = s;
}

// ---------------- out[n,d] = (sum_m qp[n,m] ctx[m,d]) / denom[n] -> attn[b,n,h,d] ----------------
__global__ void __launch_bounds__(256) gemm_out(
    const float* __restrict__ QP, const float* __restrict__ CT,
    const float* __restrict__ D, float* __restrict__ AT) {
    __shared__ float As[16][128];
    __shared__ float Bs[16][64];
    const int tid = threadIdx.x;
    const int bh = blockIdx.z;
    const int b = bh >> 3, hh = bh & 7;
    const float* A = QP + (long)bh * NPIX * MP;       // lda = MP
    const float* B = CT + (long)bh * MP * DH;         // [MP][64]
    const int bm = blockIdx.x * 128;
    const int tx = tid & 15, ty = tid >> 4;
    float acc[8][4] = {};
    for (int k0 = 0; k0 < MP; k0 += 16) {
        #pragma unroll
        for (int i = 0; i < 2; i++) {
            int s = tid + i * 256;
            int r = s >> 2, c4 = (s & 3) << 2;
            float4 v = *(const float4*)(A + (long)(bm + r) * MP + k0 + c4);
            As[c4 + 0][r] = v.x; As[c4 + 1][r] = v.y; As[c4 + 2][r] = v.z; As[c4 + 3][r] = v.w;
        }
        {
            int r = tid >> 4, c4 = (tid & 15) << 2;
            float4 v = *(const float4*)(B + (long)(k0 + r) * DH + c4);
            Bs[r][c4 + 0] = v.x; Bs[r][c4 + 1] = v.y; Bs[r][c4 + 2] = v.z; Bs[r][c4 + 3] = v.w;
        }
        __syncthreads();
        #pragma unroll
        for (int kk = 0; kk < 16; kk++) {
            float a[8], bb[4];
            *(float4*)&a[0] = *(const float4*)&As[kk][ty * 8];
            *(float4*)&a[4] = *(const float4*)&As[kk][ty * 8 + 4];
            *(float4*)&bb[0] = *(const float4*)&Bs[kk][tx * 4];
            #pragma unroll
            for (int i = 0; i < 8; i++)
                #pragma unroll
                for (int j = 0; j < 4; j++)
                    acc[i][j] = fmaf(a[i], bb[j], acc[i][j]);
        }
        __syncthreads();
    }
    #pragma unroll
    for (int i = 0; i < 8; i++) {
        int n = bm + ty * 8 + i;
        float rd = 1.0f / D[bh * NPIX + n];
        #pragma unroll
        for (int j = 0; j < 4; j++) {
            int d = tx * 4 + j;
            AT[((long)(b * NPIX + n)) * INNER + hh * DH + d] = acc[i][j] * rd;
        }
    }
}

// ---------------- group norm + NHWC(row=b*n) -> NCHW ----------------
__global__ void groupnorm_kernel(const float* __restrict__ Y, const float* __restrict__ G,
                                 const float* __restrict__ Bt, float* __restrict__ Z) {
    int b = blockIdx.x >> 3, grp = blockIdx.x & 7;
    const int CPG = 24, NELEM = CPG * NPIX;
    float s = 0.f, s2 = 0.f;
    for (int t = threadIdx.x; t < NELEM; t += 256) {
        int c = grp * CPG + (t % CPG);
        int pix = t / CPG;
        float v = Y[((long)b * NPIX + pix) * DIM + c];
        s += v; s2 += v * v;
    }
    __shared__ float ssum[8], ssq[8];
    int lane = threadIdx.x & 31, wid = threadIdx.x >> 5;
    s = warpSum(s); s2 = warpSum(s2);
    if (lane == 0) { ssum[wid] = s; ssq[wid] = s2; }
    __syncthreads();
    if (wid == 0) {
        float a = (lane < 8) ? ssum[lane] : 0.f;
        float b2 = (lane < 8) ? ssq[lane] : 0.f;
        a = warpSum(a); b2 = warpSum(b2);
        if (lane == 0) { ssum[0] = a; ssq[0] = b2; }
    }
    __syncthreads();
    float mu = ssum[0] / NELEM;
    float var = ssq[0] / NELEM - mu * mu;
    float rstd = rsqrtf(var + 1e-5f);
    for (int t = threadIdx.x; t < NELEM; t += 256) {
        int c = grp * CPG + (t % CPG);
        int pix = t / CPG;
        float v = Y[((long)b * NPIX + pix) * DIM + c];
        Z[((long)(b * DIM + c)) * NPIX + pix] = (v - mu) * rstd * G[c] + Bt[c];
    }
}

// ---------------- circular grouped conv + gelu (templated on geometry) ----------------
// CIN_G in-channels/group, COUT_G out-channels/group, KS kernel, PAD = KS/2, HALO = 16+2*PAD
template<int CIN_G, int COUT_G, int KS, int CIN_TOTAL, int COUT_TOTAL, bool DO_GELU>
__global__ void __launch_bounds__(256) conv_circ(
    const float* __restrict__ IN, const float* __restrict__ W,
    const float* __restrict__ Bi, float* __restrict__ OUT) {
    const int PAD = KS / 2;
    const int HALO = 16 + 2 * PAD;
    __shared__ float s_in[HALO * HALO];
    __shared__ float s_w[COUT_G * KS * KS];
    int tile = blockIdx.x;
    int ty0 = (tile >> 2) * 16, tx0 = (tile & 3) * 16;
    int g = blockIdx.y, b = blockIdx.z;
    int tid = threadIdx.x;
    int tx = tid & 15, ty = tid >> 4;
    float acc[COUT_G];
    #pragma unroll
    for (int co = 0; co < COUT_G; co++) acc[co] = Bi[g * COUT_G + co];
    for (int ci = 0; ci < CIN_G; ci++) {
        for (int t = tid; t < HALO * HALO; t += 256) {
            int r = t / HALO, c = t % HALO;
            int gy = (ty0 + r - PAD) & 63;
            int gx = (tx0 + c - PAD) & 63;
            s_in[t] = IN[(((long)b * CIN_TOTAL + g * CIN_G + ci) * 64 + gy) * 64 + gx];
        }
        for (int t = tid; t < COUT_G * KS * KS; t += 256) {
            int co = t / (KS * KS), r = t % (KS * KS);
            s_w[t] = W[(((long)(g * COUT_G + co)) * CIN_G + ci) * (KS * KS) + r];
        }
        __syncthreads();
        #pragma unroll
        for (int ky = 0; ky < KS; ky++) {
            #pragma unroll
            for (int kx = 0; kx < KS; kx++) {
                float v = s_in[(ty + ky) * HALO + tx + kx];
                #pragma unroll
                for (int co = 0; co < COUT_G; co++)
                    acc[co] = fmaf(v, s_w[co * KS * KS + ky * KS + kx], acc[co]);
            }
        }
        __syncthreads();
    }
    #pragma unroll
    for (int co = 0; co < COUT_G; co++) {
        float v = DO_GELU ? gelu_exact(acc[co]) : acc[co];
        OUT[(((long)b * COUT_TOTAL + g * COUT_G + co) * 64 + ty0 + ty) * 64 + tx0 + tx] = v;
    }
}

// ---------------- 1x1 conv 48->3 + bias, write final [b, t=1, y, x, c] ----------------
__global__ void conv1_kernel(const float* __restrict__ IN, const float* __restrict__ W,
                             const float* __restrict__ Bi, float* __restrict__ OUT) {
    int b = blockIdx.y;
    int pix = blockIdx.x * 256 + threadIdx.x;
    float a0 = Bi[0], a1 = Bi[1], a2 = Bi[2];
    #pragma unroll
    for (int c = 0; c < 48; c++) {
        float v = IN[((long)b * 48 + c) * NPIX + pix];
        a0 = fmaf(v, W[0 * 48 + c], a0);
        a1 = fmaf(v, W[1 * 48 + c], a1);
        a2 = fmaf(v, W[2 * 48 + c], a2);
    }
    long base = ((long)b * NPIX + pix) * 3;
    OUT[base + 0] = a0; OUT[base + 1] = a1; OUT[base + 2] = a2;
}

// ---------------- host ----------------
extern "C" void kernel_launch(void* const* d_in, const int* in_sizes, int n_in,
                              void* d_out, int out_size) {
    const float* x        = (const float*)d_in[0];
    const float* to_in_w  = (const float*)d_in[1];
    const float* to_in_b  = (const float*)d_in[2];
    const float* pos_emb  = (const float*)d_in[3];
    const float* proj     = (const float*)d_in[4];
    const float* sn_attn_g= (const float*)d_in[5];
    const float* wq       = (const float*)d_in[6];
    const float* wk       = (const float*)d_in[7];
    const float* wv       = (const float*)d_in[8];
    const float* wo       = (const float*)d_in[9];
    const float* bo       = (const float*)d_in[10];
    const float* sn_ff_g  = (const float*)d_in[11];
    const float* w1       = (const float*)d_in[12];
    const float* b1       = (const float*)d_in[13];
    const float* w2       = (const float*)d_in[14];
    const float* b2       = (const float*)d_in[15];
    const float* expand_w = (const float*)d_in[16];
    const float* fwd_w    = (const float*)d_in[17];
    const float* dec_lin_w= (const float*)d_in[18];
    const float* dec_lin_b= (const float*)d_in[19];
    const float* gn_g     = (const float*)d_in[20];
    const float* gn_b     = (const float*)d_in[21];
    const float* c9_w     = (const float*)d_in[22];
    const float* c9_b     = (const float*)d_in[23];
    const float* c7_w     = (const float*)d_in[24];
    const float* c7_b     = (const float*)d_in[25];
    const float* c5_w     = (const float*)d_in[26];
    const float* c5_b     = (const float*)d_in[27];
    const float* c1_w     = (const float*)d_in[28];
    const float* c1_b     = (const float*)d_in[29];
    float* out = (float*)d_out;

    float *ph, *phn, *pq, *pk, *pv, *pqp, *pkp, *pctx, *pksum, *pkmax, *pkmp, *pksp,
          *pden, *pattn, *pff, *pt1, *pt2, *py, *pnchw, *pc9, *pc7, *pc5;
    cudaGetSymbolAddress((void**)&ph, g_h);
    cudaGetSymbolAddress((void**)&phn, g_hn);
    cudaGetSymbolAddress((void**)&pq, g_q);
    cudaGetSymbolAddress((void**)&pk, g_k);
    cudaGetSymbolAddress((void**)&pv, g_v);
    cudaGetSymbolAddress((void**)&pqp, g_qp);
    cudaGetSymbolAddress((void**)&pkp, g_kp);
    cudaGetSymbolAddress((void**)&pctx, g_ctx);
    cudaGetSymbolAddress((void**)&pksum, g_ksum);
    cudaGetSymbolAddress((void**)&pkmax, g_kmax);
    cudaGetSymbolAddress((void**)&pkmp, g_kmpart);
    cudaGetSymbolAddress((void**)&pksp, g_kspart);
    cudaGetSymbolAddress((void**)&pden, g_denom);
    cudaGetSymbolAddress((void**)&pattn, g_attn);
    cudaGetSymbolAddress((void**)&pff, g_ff);
    cudaGetSymbolAddress((void**)&pt1, g_t1);
    cudaGetSymbolAddress((void**)&pt2, g_t2);
    cudaGetSymbolAddress((void**)&py, g_y);
    cudaGetSymbolAddress((void**)&pnchw, g_nchw);
    cudaGetSymbolAddress((void**)&pc9, g_c9o);
    cudaGetSymbolAddress((void**)&pc7, g_c7o);
    cudaGetSymbolAddress((void**)&pc5, g_c5o);

    embed_kernel<<<ROWS, DIM>>>(x, to_in_w, to_in_b, pos_emb, ph);

    for (int i = 0; i < DEPTH; i++) {
        const float* proj_i = proj + (long)i * MFEAT * DH;
        scalenorm_kernel<<<2048, 256>>>(ph, phn, sn_attn_g, i);
        gemm_nt<0><<<dim3(128, 8), 256>>>(phn, wq + (long)i * INNER * DIM, nullptr, nullptr, pq, ROWS, INNER, DIM);
        gemm_nt<0><<<dim3(128, 8), 256>>>(phn, wk + (long)i * INNER * DIM, nullptr, nullptr, pk, ROWS, INNER, DIM);
        gemm_nt<0><<<dim3(128, 8), 256>>>(phn, wv + (long)i * INNER * DIM, nullptr, nullptr, pv, ROWS, INNER, DIM);
        gemm_dd<<<dim3(32, 5, BHN), 256>>>(pq, proj_i, pqp);
        gemm_dd<<<dim3(32, 5, BHN), 256>>>(pk, proj_i, pkp);
        kmax_part_kernel<<<dim3(32, BHN), 256>>>(pkp, pkmp);
        kmax_fin_kernel<<<BHN, 32>>>(pkmp, pkmax);
        finalize_kernel<true ><<<16384, 256>>>(pq, pqp, nullptr);
        finalize_kernel<false><<<16384, 256>>>(pk, pkp, pkmax);
        gemm_ctx<<<dim3(5, 1, BHN), 256>>>(pkp, pv, pctx);
        ksum_part_kernel<<<dim3(8, BHN), MP>>>(pkp, pksp);
        ksum_fin_kernel<<<BHN, MP>>>(pksp, pksum);
        denom_kernel<<<16384, 256>>>(pqp, pksum, pden);
        gemm_out<<<dim3(32, 1, BHN), 256>>>(pqp, pctx, pden, pattn);
        gemm_nt<3><<<dim3(128, 3), 256>>>(pattn, wo + (long)i * DIM * INNER, bo + (long)i * DIM, ph, ph, ROWS, DIM, INNER);
        scalenorm_kernel<<<2048, 256>>>(ph, phn, sn_ff_g, i);
        gemm_nt<2><<<dim3(128, 12), 256>>>(phn, w1 + (long)i * FF * DIM, b1 + (long)i * FF, nullptr, pff, ROWS, FF, DIM);
        gemm_nt<3><<<dim3(128, 3), 256>>>(pff, w2 + (long)i * DIM * FF, b2 + (long)i * DIM, ph, ph, ROWS, DIM, FF);
    }

    gemm_nt<0><<<dim3(128, 3), 256>>>(ph, expand_w, nullptr, nullptr, pt1, ROWS, DIM, DIM);
    gemm_nt<0><<<dim3(128, 3), 256>>>(pt1, fwd_w, nullptr, nullptr, pt2, ROWS, DIM, DIM);
    gemm_nt<1><<<dim3(128, 3), 256>>>(pt2, dec_lin_w, dec_lin_b, nullptr, py, ROWS, DIM, DIM);

    groupnorm_kernel<<<32, 256>>>(py, gn_g, gn_b, pnchw);
    conv_circ<24, 24, 9, 192, 192, true><<<dim3(16, 8, 4), 256>>>(pnchw, c9_w, c9_b, pc9);
    conv_circ<24, 12, 7, 192,  96, true><<<dim3(16, 8, 4), 256>>>(pc9, c7_w, c7_b, pc7);
    conv_circ<12,  6, 5,  96,  48, true><<<dim3(16, 8, 4), 256>>>(pc7, c5_w, c5_b, pc5);
    conv1_kernel<<<dim3(16, 4), 256>>>(pc5, c1_w, c1_b, out);
}